// round 15
// baseline (speedup 1.0000x reference)
#include <cuda_runtime.h>
#include <cuda_bf16.h>
#include <cstdint>

// conv_layer_65000035058096 — 3xBF16 mma.sync gather-GEMM (baseline PTX)
// D = xh*wh + xh*wl + xl*wh (bf16 hi/lo split, fp32 accum, err ~2^-18)
// R15: x pre-split into bf16 hi/lo planes (no cvt in main loop), A fragments
// via ldmatrix.x4 (48B-stride conflict-free), 128-thread CTAs x 5/SM (20 warps),
// warp tile m32 x n64 (R12 champion shape), smem-staged B, double buffering.

#define V_TOT 163842
#define NCH 28            // k-steps of 16
#define NX8 2621472       // 2*V*64/8

// B fragments, mma m16n8k16 register layout, hi/lo packed:
__device__ uint4 g_Bf[NCH * 8 * 32];
// x split planes, elementwise bf16: g_xh4[e8] = 8 hi bf16, g_xl4 = 8 lo bf16
__device__ uint4 g_xh4[NX8];
__device__ uint4 g_xl4[NX8];

__device__ __forceinline__ uint32_t pack_bf16_hi_lo(float hi_elem, float lo_elem) {
    uint32_t r;
    asm("cvt.rn.bf16x2.f32 %0, %1, %2;" : "=r"(r) : "f"(hi_elem), "f"(lo_elem));
    return r;
}
__device__ __forceinline__ void cvt_pair(float2 p, uint32_t& hi2, uint32_t& lo2) {
    uint32_t h;
    asm("cvt.rn.bf16x2.f32 %0, %1, %2;" : "=r"(h) : "f"(p.y), "f"(p.x));
    float hx = __uint_as_float(h << 16);
    float hy = __uint_as_float(h & 0xFFFF0000u);
    uint32_t l;
    asm("cvt.rn.bf16x2.f32 %0, %1, %2;" : "=r"(l) : "f"(p.y - hy), "f"(p.x - hx));
    hi2 = h; lo2 = l;
}

__global__ void pack_B_kernel(const float* __restrict__ W) {
    int idx = blockIdx.x * blockDim.x + threadIdx.x;   // 7168
    if (idx < NCH * 8 * 32) {
        int l = idx & 31, nbk = (idx >> 5) & 7, s = idx >> 8;
        int g = l >> 2, tig = l & 3;
        int o = nbk * 8 + g;
        const float* wr = W + o * 448 + s * 16 + 2 * tig;
        float v[4] = { wr[0], wr[1], wr[8], wr[9] };
        float h[4], lo[4];
#pragma unroll
        for (int i = 0; i < 4; ++i) {
            __nv_bfloat16 hb = __float2bfloat16_rn(v[i]);
            h[i] = __bfloat162float(hb);
            lo[i] = v[i] - h[i];
        }
        uint4 r;
        r.x = pack_bf16_hi_lo(h[1], h[0]);
        r.y = pack_bf16_hi_lo(h[3], h[2]);
        r.z = pack_bf16_hi_lo(lo[1], lo[0]);
        r.w = pack_bf16_hi_lo(lo[3], lo[2]);
        g_Bf[idx] = r;
    }
}

__global__ void split_x_kernel(const float* __restrict__ x) {
    int i = blockIdx.x * blockDim.x + threadIdx.x;
    if (i < NX8) {
        const float4 v0 = reinterpret_cast<const float4*>(x)[2 * i];
        const float4 v1 = reinterpret_cast<const float4*>(x)[2 * i + 1];
        uint4 h, l;
        cvt_pair(make_float2(v0.x, v0.y), h.x, l.x);
        cvt_pair(make_float2(v0.z, v0.w), h.y, l.y);
        cvt_pair(make_float2(v1.x, v1.y), h.z, l.z);
        cvt_pair(make_float2(v1.z, v1.w), h.w, l.w);
        g_xh4[i] = h;
        g_xl4[i] = l;
    }
}

__device__ __forceinline__ void cpa16(uint32_t dst, const void* src) {
    asm volatile("cp.async.cg.shared.global [%0], [%1], 16;" :: "r"(dst), "l"(src) : "memory");
}
__device__ __forceinline__ uint32_t smem_u32(const void* p) {
    uint32_t a;
    asm("{ .reg .u64 t; cvta.to.shared.u64 t, %1; cvt.u32.u64 %0, t; }" : "=r"(a) : "l"(p));
    return a;
}
#define LDSM_X4(r, addr) asm volatile( \
    "ldmatrix.sync.aligned.m8n8.x4.shared.b16 {%0,%1,%2,%3}, [%4];" \
    : "=r"((r)[0]), "=r"((r)[1]), "=r"((r)[2]), "=r"((r)[3]) : "r"(addr))
#define MMA(c, a, b0, b1) asm volatile( \
    "mma.sync.aligned.m16n8k16.row.col.f32.bf16.bf16.f32 " \
    "{%0,%1,%2,%3}, {%4,%5,%6,%7}, {%8,%9}, {%0,%1,%2,%3};" \
    : "+f"((c)[0]), "+f"((c)[1]), "+f"((c)[2]), "+f"((c)[3]) \
    : "r"((a)[0]), "r"((a)[1]), "r"((a)[2]), "r"((a)[3]), "r"(b0), "r"(b1))

// A smem: 48B-stride rows (12 words), 32B data -> ldmatrix conflict-free
#define SAW 12

__global__ __launch_bounds__(128, 5)
void sconv_bf16(const int* __restrict__ nb,
                const float* __restrict__ bias,
                float* __restrict__ out) {
    __shared__ uint32_t Ah[2][128 * SAW];   // 2 x 6144 B
    __shared__ uint32_t Al[2][128 * SAW];
    __shared__ uint4    Bs[2][256];         // 2 x 4096 B
    __shared__ int      nbs[896];           // [j][row]

    const int t    = threadIdx.x;
    const int lane = t & 31;
    const int w    = t >> 5;
    const int g    = lane >> 2;
    const int tig  = lane & 3;
    const int wv   = w << 5;            // warp vertex base (4 warps x 32 rows)
    const int batch = blockIdx.y;
    const int v0    = blockIdx.x * 128;
    const long long xbase = (long long)batch * V_TOT;

    // ---- stage neighbor indices: nbs[j*128 + r]
#pragma unroll
    for (int i = 0; i < 7; ++i) {
        int idx = t + (i << 7);
        int r = idx & 127, j = idx >> 7;
        int vv = v0 + r; if (vv >= V_TOT) vv = V_TOT - 1;
        nbs[idx] = nb[vv * 7 + j];
    }
    __syncthreads();

    const uint32_t ahb[2] = { smem_u32(&Ah[0][0]), smem_u32(&Ah[1][0]) };
    const uint32_t alb[2] = { smem_u32(&Al[0][0]), smem_u32(&Al[1][0]) };
    const uint32_t bsb[2] = { smem_u32(&Bs[0][0]), smem_u32(&Bs[1][0]) };
    const char* xh = (const char*)g_xh4;
    const char* xl = (const char*)g_xl4;
    const char* gB = (const char*)g_Bf;

    float acc[2][8][4];
#pragma unroll
    for (int rb = 0; rb < 2; ++rb)
#pragma unroll
        for (int n = 0; n < 8; ++n)
#pragma unroll
            for (int e = 0; e < 4; ++e) acc[rb][n][e] = 0.0f;

    // ldmatrix lane address pieces (within warp's 32 rows)
    const int lrow = lane & 15;
    const int loff = (lane >> 4) << 4;

    // prologue: stage chunk 0 (j=0, kb=0); thread t stages row t
    {
        const long long nbr = nbs[t];
        const char* sh = xh + ((xbase + nbr) << 7);
        const char* sl = xl + ((xbase + nbr) << 7);
        const uint32_t da = t * 48;
        cpa16(ahb[0] + da,      sh);
        cpa16(ahb[0] + da + 16, sh + 16);
        cpa16(alb[0] + da,      sl);
        cpa16(alb[0] + da + 16, sl + 16);
        cpa16(bsb[0] + t * 16,         gB + t * 16);
        cpa16(bsb[0] + (t + 128) * 16, gB + (t + 128) * 16);
        asm volatile("cp.async.commit_group;" ::: "memory");
    }

    for (int c = 0; c < NCH; ++c) {
        const int buf = c & 1;

        if (c + 1 < NCH) {
            const int cn = c + 1;
            const int j  = cn >> 2;
            const int kB = (cn & 3) << 5;     // byte offset within 128-B row
            const int bn = cn & 1;
            const long long nbr = nbs[j * 128 + t];
            const char* sh = xh + ((xbase + nbr) << 7) + kB;
            const char* sl = xl + ((xbase + nbr) << 7) + kB;
            const uint32_t da = t * 48;
            cpa16(ahb[bn] + da,      sh);
            cpa16(ahb[bn] + da + 16, sh + 16);
            cpa16(alb[bn] + da,      sl);
            cpa16(alb[bn] + da + 16, sl + 16);
            cpa16(bsb[bn] + t * 16,         gB + cn * 4096 + t * 16);
            cpa16(bsb[bn] + (t + 128) * 16, gB + cn * 4096 + (t + 128) * 16);
            asm volatile("cp.async.commit_group;" ::: "memory");
            asm volatile("cp.async.wait_group 1;" ::: "memory");
        } else {
            asm volatile("cp.async.wait_group 0;" ::: "memory");
        }
        __syncthreads();

        // ---- compute chunk c: 4 ldmatrix + 8 B-LDS.128 + 48 MMA
        uint32_t ah[2][4], al2[2][4];
#pragma unroll
        for (int rb = 0; rb < 2; ++rb) {
            const uint32_t ra = (wv + (rb << 4) + lrow) * 48 + loff;
            LDSM_X4(ah[rb],  ahb[buf] + ra);
            LDSM_X4(al2[rb], alb[buf] + ra);
        }

        const uint4* bB = &Bs[buf][0];
#pragma unroll
        for (int nblk = 0; nblk < 8; ++nblk) {
            uint4 bf = bB[(nblk << 5) + lane];
            MMA(acc[0][nblk], ah[0],  bf.x, bf.y);
            MMA(acc[1][nblk], ah[1],  bf.x, bf.y);
            MMA(acc[0][nblk], ah[0],  bf.z, bf.w);
            MMA(acc[1][nblk], ah[1],  bf.z, bf.w);
            MMA(acc[0][nblk], al2[0], bf.x, bf.y);
            MMA(acc[1][nblk], al2[1], bf.x, bf.y);
        }
        __syncthreads();   // done reading buf before re-staging
    }

    // ---- epilogue: D frags -> global (+bias)
#pragma unroll
    for (int rb = 0; rb < 2; ++rb) {
        const int vr0 = v0 + wv + (rb << 4) + g;
        const int vr1 = vr0 + 8;
#pragma unroll
        for (int nblk = 0; nblk < 8; ++nblk) {
            const int n = (nblk << 3) + 2 * tig;
            const float2 b2 = *reinterpret_cast<const float2*>(bias + n);
            if (vr0 < V_TOT)
                *reinterpret_cast<float2*>(out + ((xbase + vr0) << 6) + n) =
                    make_float2(acc[rb][nblk][0] + b2.x, acc[rb][nblk][1] + b2.y);
            if (vr1 < V_TOT)
                *reinterpret_cast<float2*>(out + ((xbase + vr1) << 6) + n) =
                    make_float2(acc[rb][nblk][2] + b2.x, acc[rb][nblk][3] + b2.y);
        }
    }
}

extern "C" void kernel_launch(void* const* d_in, const int* in_sizes, int n_in,
                              void* d_out, int out_size) {
    const float* x   = (const float*)d_in[0];   // (2, V, 64) f32
    const int*   nbi = (const int*)d_in[1];     // (V*7,) i32
    const float* W   = (const float*)d_in[2];   // (64, 448) f32
    const float* b   = (const float*)d_in[3];   // (64,) f32
    float*       out = (float*)d_out;           // (2, V, 64) f32

    pack_B_kernel<<<(NCH * 8 * 32 + 255) / 256, 256>>>(W);
    split_x_kernel<<<(NX8 + 255) / 256, 256>>>(x);

    dim3 grid((V_TOT + 127) / 128, 2);
    sconv_bf16<<<grid, 128>>>(nbi, b, out);
}

// round 16
// speedup vs baseline: 1.5665x; 1.5665x over previous
#include <cuda_runtime.h>
#include <cuda_fp16.h>
#include <cstdint>

// conv_layer_65000035058096 — 2xFP16 mma.sync gather-GEMM (baseline PTX)
// D = x_fp16*wh + x_fp16*wl  (W split into fp16 hi+lo; x single fp16)
// error ~2^-11/sqrt(3) ~ 2.8e-4 norm-relative (threshold 1e-3).
// R16 = R12 champion structure (warp m32 x n64, CTA 256 v, double-buffered
// cp.async) with 2-term fp16 math: 32 MMAs/chunk/warp (was 48), 1-op cvt.

#define V_TOT 163842
#define NCH 28            // k-steps of 16
#define SA 20             // As row stride in words (16 data + 4 pad)
#define TILE_V 256

// B fragments, mma m16n8k16 register layout, wh/wl packed:
// g_Bf[(s*8+nb)*32 + lane] = {wh0, wh1, wl0, wl1}
__device__ uint4 g_Bf[NCH * 8 * 32];

__device__ __forceinline__ uint32_t pack_f16x2(float hi_elem, float lo_elem) {
    uint32_t r;
    asm("cvt.rn.f16x2.f32 %0, %1, %2;" : "=r"(r) : "f"(hi_elem), "f"(lo_elem));
    return r;
}

__global__ void pack_B_kernel(const float* __restrict__ W) {
    int idx = blockIdx.x * blockDim.x + threadIdx.x;   // 7168
    if (idx < NCH * 8 * 32) {
        int l = idx & 31, nbk = (idx >> 5) & 7, s = idx >> 8;
        int g = l >> 2, tig = l & 3;
        int o = nbk * 8 + g;
        const float* wr = W + o * 448 + s * 16 + 2 * tig;
        float v[4] = { wr[0], wr[1], wr[8], wr[9] };   // k: 2tig,2tig+1,2tig+8,2tig+9
        float h[4], lo[4];
#pragma unroll
        for (int i = 0; i < 4; ++i) {
            __half hb = __float2half_rn(v[i]);
            h[i] = __half2float(hb);
            lo[i] = v[i] - h[i];
        }
        uint4 r;
        r.x = pack_f16x2(h[1], h[0]);      // low half = k even
        r.y = pack_f16x2(h[3], h[2]);
        r.z = pack_f16x2(lo[1], lo[0]);
        r.w = pack_f16x2(lo[3], lo[2]);
        g_Bf[idx] = r;
    }
}

__device__ __forceinline__ void cpa16(uint32_t dst, const void* src) {
    asm volatile("cp.async.cg.shared.global [%0], [%1], 16;" :: "r"(dst), "l"(src) : "memory");
}
__device__ __forceinline__ uint32_t smem_u32(const void* p) {
    uint32_t a;
    asm("{ .reg .u64 t; cvta.to.shared.u64 t, %1; cvt.u32.u64 %0, t; }" : "=r"(a) : "l"(p));
    return a;
}
#define MMA(c, a, b0, b1) asm volatile( \
    "mma.sync.aligned.m16n8k16.row.col.f32.f16.f16.f32 " \
    "{%0,%1,%2,%3}, {%4,%5,%6,%7}, {%8,%9}, {%0,%1,%2,%3};" \
    : "+f"((c)[0]), "+f"((c)[1]), "+f"((c)[2]), "+f"((c)[3]) \
    : "r"((a)[0]), "r"((a)[1]), "r"((a)[2]), "r"((a)[3]), "r"(b0), "r"(b1))

// dynamic smem: As 2*256*20*4 = 40960 | Bs 2*4096 = 8192 | nbs 1792*4 = 7168
#define OFF_BS  40960
#define OFF_NBS 49152
#define SMEM_REQ 56320

__global__ __launch_bounds__(256, 2)
void sconv_f16(const float* __restrict__ x,
               const int* __restrict__ nb,
               const float* __restrict__ bias,
               float* __restrict__ out) {
    extern __shared__ char dsm[];
    float* As  = (float*)dsm;                 // [2][256*SA]
    uint4* Bs  = (uint4*)(dsm + OFF_BS);      // [2][256]
    int*   nbs = (int*)(dsm + OFF_NBS);       // [7][256]
    const uint32_t asb = smem_u32(dsm);
    const uint32_t bsb = asb + OFF_BS;

    const int t    = threadIdx.x;
    const int lane = t & 31;
    const int w    = t >> 5;
    const int g    = lane >> 2;
    const int tig  = lane & 3;
    const int wv   = w << 5;            // warp vertex base (32 v per warp)
    const int batch = blockIdx.y;
    const int v0    = blockIdx.x * TILE_V;
    const long long xbase = (long long)batch * V_TOT;

    // ---- stage neighbor indices: nbs[j*256 + r]
#pragma unroll
    for (int i = 0; i < 7; ++i) {
        int idx = t + (i << 8);
        int r = idx & 255, j = idx >> 8;
        int vv = v0 + r; if (vv >= V_TOT) vv = V_TOT - 1;
        nbs[idx] = nb[vv * 7 + j];
    }
    __syncthreads();

    // acc[rb][nblk][e]: row block rb (rows wv+16rb..+15)
    float acc[2][8][4];
#pragma unroll
    for (int rb = 0; rb < 2; ++rb)
#pragma unroll
        for (int n = 0; n < 8; ++n)
#pragma unroll
            for (int e = 0; e < 4; ++e) acc[rb][n][e] = 0.0f;

    // staging: 1024 (row,quad) tasks over 256 threads x 4
    // prologue: stage chunk 0 (j=0, kb=0)
    {
#pragma unroll
        for (int i = 0; i < 4; ++i) {
            int idx = t + (i << 8);
            int row = idx >> 2, q = idx & 3;
            cpa16(asb + (row * SA + (q << 2)) * 4,
                  x + ((xbase + nbs[row]) << 6) + (q << 2));
        }
        cpa16(bsb + t * 16, (const char*)g_Bf + t * 16);
        asm volatile("cp.async.commit_group;" ::: "memory");
    }

    for (int c = 0; c < NCH; ++c) {
        const int buf = c & 1;

        if (c + 1 < NCH) {
            const int cn = c + 1;
            const int j  = cn >> 2;
            const int kb = (cn & 3) << 4;
            const int bn = cn & 1;
            const uint32_t ad = asb + bn * (TILE_V * SA * 4);
#pragma unroll
            for (int i = 0; i < 4; ++i) {
                int idx = t + (i << 8);
                int row = idx >> 2, q = idx & 3;
                cpa16(ad + (row * SA + (q << 2)) * 4,
                      x + ((xbase + nbs[j * 256 + row]) << 6) + kb + (q << 2));
            }
            cpa16(bsb + bn * 4096 + t * 16, (const char*)g_Bf + cn * 4096 + t * 16);
            asm volatile("cp.async.commit_group;" ::: "memory");
            asm volatile("cp.async.wait_group 1;" ::: "memory");
        } else {
            asm volatile("cp.async.wait_group 0;" ::: "memory");
        }
        __syncthreads();

        // ---- compute chunk c: 2 row blocks share the B fragments
        const float* aB = As + buf * (TILE_V * SA);
        uint32_t af[2][4];
#pragma unroll
        for (int rb = 0; rb < 2; ++rb) {
            const int r0 = (wv + (rb << 4) + g) * SA;
            const int r1 = r0 + 8 * SA;
            float2 p00 = *reinterpret_cast<const float2*>(aB + r0 + 2 * tig);
            float2 p10 = *reinterpret_cast<const float2*>(aB + r1 + 2 * tig);
            float2 p01 = *reinterpret_cast<const float2*>(aB + r0 + 2 * tig + 8);
            float2 p11 = *reinterpret_cast<const float2*>(aB + r1 + 2 * tig + 8);
            af[rb][0] = pack_f16x2(p00.y, p00.x);
            af[rb][1] = pack_f16x2(p10.y, p10.x);
            af[rb][2] = pack_f16x2(p01.y, p01.x);
            af[rb][3] = pack_f16x2(p11.y, p11.x);
        }

        const uint4* bB = Bs + buf * 256;
#pragma unroll
        for (int nblk = 0; nblk < 8; ++nblk) {
            uint4 bf = bB[(nblk << 5) + lane];
            MMA(acc[0][nblk], af[0], bf.x, bf.y);   // x * wh
            MMA(acc[1][nblk], af[1], bf.x, bf.y);
            MMA(acc[0][nblk], af[0], bf.z, bf.w);   // x * wl
            MMA(acc[1][nblk], af[1], bf.z, bf.w);
        }
        __syncthreads();   // done reading buf before it is re-staged
    }

    // ---- epilogue: D frags -> global (+bias)
#pragma unroll
    for (int rb = 0; rb < 2; ++rb) {
        const int vr0 = v0 + wv + (rb << 4) + g;
        const int vr1 = vr0 + 8;
#pragma unroll
        for (int nblk = 0; nblk < 8; ++nblk) {
            const int n = (nblk << 3) + 2 * tig;
            const float2 b2 = *reinterpret_cast<const float2*>(bias + n);
            if (vr0 < V_TOT)
                *reinterpret_cast<float2*>(out + ((xbase + vr0) << 6) + n) =
                    make_float2(acc[rb][nblk][0] + b2.x, acc[rb][nblk][1] + b2.y);
            if (vr1 < V_TOT)
                *reinterpret_cast<float2*>(out + ((xbase + vr1) << 6) + n) =
                    make_float2(acc[rb][nblk][2] + b2.x, acc[rb][nblk][3] + b2.y);
        }
    }
}

extern "C" void kernel_launch(void* const* d_in, const int* in_sizes, int n_in,
                              void* d_out, int out_size) {
    const float* x   = (const float*)d_in[0];   // (2, V, 64) f32
    const int*   nbi = (const int*)d_in[1];     // (V*7,) i32
    const float* W   = (const float*)d_in[2];   // (64, 448) f32
    const float* b   = (const float*)d_in[3];   // (64,) f32
    float*       out = (float*)d_out;           // (2, V, 64) f32

    cudaFuncSetAttribute(sconv_f16, cudaFuncAttributeMaxDynamicSharedMemorySize, SMEM_REQ);

    pack_B_kernel<<<(NCH * 8 * 32 + 255) / 256, 256>>>(W);

    dim3 grid((V_TOT + TILE_V - 1) / TILE_V, 2);
    sconv_f16<<<grid, 256, SMEM_REQ>>>(x, nbi, b, out);
}